// round 13
// baseline (speedup 1.0000x reference)
#include <cuda_runtime.h>
#include <cuda_fp16.h>
#include <math.h>

#define Bb 4
#define Ss 2048
#define Ee 1024
#define Hh 16
#define Dd 64
#define MTOK (Bb*Ss)
#define BH   (Bb*Hh)

#define QSCALE 0.1803368801111204f   // 0.125 * log2(e)

// ---------------- scratch ----------------
__device__ __half g_xq[(size_t)MTOK*Ee];
__device__ __half g_xk[(size_t)MTOK*Ee];
__device__ __half g_xv[(size_t)MTOK*Ee];
__device__ __half g_wq[(size_t)Ee*Ee];
__device__ __half g_wk[(size_t)Ee*Ee];
__device__ __half g_wv[(size_t)Ee*Ee];
__device__ __half g_wo[(size_t)Ee*Ee];
__device__ __half g_Qh[(size_t)BH*Ss*Dd];
__device__ __half g_Kh[(size_t)BH*Ss*Dd];
__device__ __half g_Vh[(size_t)BH*Ss*Dd];
__device__ __half g_ctxh[(size_t)Bb*Ss*Ee];
__device__ float  g_attn_fb[(size_t)BH*Ss*Ss];

__device__ __forceinline__ void mma16816(float& c0, float& c1, float& c2, float& c3,
                                         unsigned a0, unsigned a1, unsigned a2, unsigned a3,
                                         unsigned b0, unsigned b1)
{
    asm volatile(
        "mma.sync.aligned.m16n8k16.row.col.f32.f16.f16.f32 "
        "{%0,%1,%2,%3}, {%4,%5,%6,%7}, {%8,%9}, {%0,%1,%2,%3};\n"
        : "+f"(c0), "+f"(c1), "+f"(c2), "+f"(c3)
        : "r"(a0), "r"(a1), "r"(a2), "r"(a3), "r"(b0), "r"(b1));
}
__device__ __forceinline__ unsigned f2h2(float a, float b) {
    __half2 h = __floats2half2_rn(a, b);
    return *(unsigned*)&h;
}
__device__ __forceinline__ float ex2f(float x) {
    float y; asm("ex2.approx.f32 %0, %1;" : "=f"(y) : "f"(x)); return y;
}
__device__ __forceinline__ unsigned h2ex2(unsigned x) {
    unsigned y; asm("ex2.approx.f16x2 %0, %1;" : "=r"(y) : "r"(x)); return y;
}
__device__ __forceinline__ void cp16(void* smem, const void* gmem) {
    unsigned s = (unsigned)__cvta_generic_to_shared(smem);
    asm volatile("cp.async.cg.shared.global [%0], [%1], 16;" :: "r"(s), "l"(gmem));
}
__device__ __forceinline__ void cp16s(unsigned saddr, const void* gmem) {
    asm volatile("cp.async.cg.shared.global [%0], [%1], 16;" :: "r"(saddr), "l"(gmem));
}
__device__ __forceinline__ void cp_commit() { asm volatile("cp.async.commit_group;"); }
template<int N> __device__ __forceinline__ void cp_wait() {
    asm volatile("cp.async.wait_group %0;" :: "n"(N));
}
__device__ __forceinline__ void ldsm_x4(unsigned& r0, unsigned& r1, unsigned& r2, unsigned& r3,
                                        const __half* p) {
    unsigned s = (unsigned)__cvta_generic_to_shared(p);
    asm volatile("ldmatrix.sync.aligned.m8n8.x4.shared.b16 {%0,%1,%2,%3}, [%4];"
        : "=r"(r0), "=r"(r1), "=r"(r2), "=r"(r3) : "r"(s));
}
__device__ __forceinline__ void ldsm_x4s(unsigned& r0, unsigned& r1, unsigned& r2, unsigned& r3,
                                         unsigned saddr) {
    asm volatile("ldmatrix.sync.aligned.m8n8.x4.shared.b16 {%0,%1,%2,%3}, [%4];"
        : "=r"(r0), "=r"(r1), "=r"(r2), "=r"(r3) : "r"(saddr));
}
__device__ __forceinline__ void ldsm_x4t(unsigned& r0, unsigned& r1, unsigned& r2, unsigned& r3,
                                         const __half* p) {
    unsigned s = (unsigned)__cvta_generic_to_shared(p);
    asm volatile("ldmatrix.sync.aligned.m8n8.x4.trans.shared.b16 {%0,%1,%2,%3}, [%4];"
        : "=r"(r0), "=r"(r1), "=r"(r2), "=r"(r3) : "r"(s));
}
__device__ __forceinline__ void stg_cs_v2(float* p, float a, float b) {
    asm volatile("st.global.cs.v2.f32 [%0], {%1, %2};" :: "l"(p), "f"(a), "f"(b) : "memory");
}
__device__ __forceinline__ unsigned swz128(unsigned x) { return x ^ ((x >> 3) & 0x70u); }

// ============================================================================
// fused fp32->fp16 conversion of all inputs + weights
// ============================================================================
#define IN4 ((int)((size_t)MTOK*Ee/4))
#define W4  ((int)((size_t)Ee*Ee/4))
#define IN_BLK (IN4/256)
#define W_BLK  (W4/256)

__global__ __launch_bounds__(256)
void f2h_all_kernel(const float* __restrict__ q, const float* __restrict__ k,
                    const float* __restrict__ v, const float* __restrict__ wq,
                    const float* __restrict__ wk, const float* __restrict__ wv,
                    const float* __restrict__ wo,
                    __half* xq, __half* xk, __half* xv,
                    __half* hq, __half* hk, __half* hv, __half* ho)
{
    int blk = blockIdx.x;
    const float* src; __half* dst;
    if      (blk < 1*IN_BLK)          { src = q;  dst = xq; blk -= 0; }
    else if (blk < 2*IN_BLK)          { src = k;  dst = xk; blk -= 1*IN_BLK; }
    else if (blk < 3*IN_BLK)          { src = v;  dst = xv; blk -= 2*IN_BLK; }
    else if (blk < 3*IN_BLK + W_BLK)  { src = wq; dst = hq; blk -= 3*IN_BLK; }
    else if (blk < 3*IN_BLK + 2*W_BLK){ src = wk; dst = hk; blk -= 3*IN_BLK + W_BLK; }
    else if (blk < 3*IN_BLK + 3*W_BLK){ src = wv; dst = hv; blk -= 3*IN_BLK + 2*W_BLK; }
    else                              { src = wo; dst = ho; blk -= 3*IN_BLK + 3*W_BLK; }
    const int i = blk * 256 + threadIdx.x;
    float4 val = ((const float4*)src)[i];
    ((__half2*)dst)[2*i]     = __floats2half2_rn(val.x, val.y);
    ((__half2*)dst)[2*i + 1] = __floats2half2_rn(val.z, val.w);
}

// ============================================================================
// proj16: C = A @ W^T + bias. BK=64 (128B SW128 rows), 3-stage cp.async ring,
// ONE barrier per 64-wide k-chunk. Dynamic smem 96KB, 2 CTAs/SM.
// MODE 0: z selects (q,k,v); fp16 head layout out, scaled. MODE 1: fp32 out.
// ============================================================================
#define PST2 16384                  // bytes per stage per matrix (128 x 128B)
#define PROJ_SMEM (6*PST2)          // 98,304 B

template<int MODE>
__global__ __launch_bounds__(256)
void proj16_kernel(const __half* __restrict__ A0, const __half* __restrict__ A1,
                   const __half* __restrict__ A2,
                   const __half* __restrict__ W0, const __half* __restrict__ W1,
                   const __half* __restrict__ W2,
                   const float* __restrict__ b0p, const float* __restrict__ b1p,
                   const float* __restrict__ b2p,
                   void* d0, void* d1, void* d2)
{
    extern __shared__ __align__(128) unsigned char psm[];
    unsigned char* smA = psm;                 // 3 stages of A
    unsigned char* smB = psm + 3*PST2;        // 3 stages of B

    const __half* A; const __half* W; const float* bias; void* dst_; float scale;
    if (MODE == 0) {
        const int z = blockIdx.z;
        if (z == 0)      { A = A0; W = W0; bias = b0p; dst_ = d0; scale = QSCALE; }
        else if (z == 1) { A = A1; W = W1; bias = b1p; dst_ = d1; scale = 1.0f; }
        else             { A = A2; W = W2; bias = b2p; dst_ = d2; scale = 1.0f; }
    } else {
        A = A0; W = W0; bias = b0p; dst_ = d0; scale = 1.0f;
    }

    const int bm = blockIdx.y * 128;
    const int bn = blockIdx.x * 128;
    const int tid = threadIdx.x;
    const int warp = tid >> 5;
    const int lane = tid & 31;
    const int wm = warp >> 2;
    const int wn = warp & 3;
    const int g  = lane >> 2;
    const int t2 = (lane & 3) * 2;
    const int a_r  = lane & 15;
    const int a_cc = (lane >> 4) & 1;
    const int r8    = lane & 7;
    const int sel_k = (lane >> 3) & 1;
    const int sel_n = (lane >> 4) & 1;

    float acc[4][4][4] = {};

    // stage one 64-wide k-chunk (128 rows x 128 B per matrix)
    auto stage = [&](int kt, int s) {
        const int k0 = kt * 64;
        const unsigned ab = (unsigned)__cvta_generic_to_shared(smA + s*PST2);
        const unsigned bb = (unsigned)__cvta_generic_to_shared(smB + s*PST2);
#pragma unroll
        for (int i = 0; i < 4; i++) {
            const int idx = tid + 256*i;            // 0..1023
            const int r = idx >> 3;                 // row 0..127
            const int c = (idx & 7) * 16;           // byte col 0..112
            const unsigned off = swz128((unsigned)(r*128 + c));
            cp16s(ab + off, A + (size_t)(bm + r) * Ee + k0 + (c >> 1));
            cp16s(bb + off, W + (size_t)(bn + r) * Ee + k0 + (c >> 1));
        }
    };

    const int NK = Ee/64;   // 16
    stage(0, 0); cp_commit();
    stage(1, 1); cp_commit();

    for (int kt = 0; kt < NK; kt++) {
        if (kt + 1 < NK) cp_wait<1>(); else cp_wait<0>();
        __syncthreads();
        if (kt + 2 < NK) { stage(kt + 2, (kt + 2) % 3); cp_commit(); }

        const unsigned Ab = (unsigned)__cvta_generic_to_shared(smA + (kt % 3) * PST2);
        const unsigned Bbp = (unsigned)__cvta_generic_to_shared(smB + (kt % 3) * PST2);

#pragma unroll
        for (int ks = 0; ks < 4; ks++) {            // 4 x 16-col slabs
            unsigned af[4][4], bf[4][2];
#pragma unroll
            for (int mt = 0; mt < 4; mt++) {
                const int row = wm*64 + mt*16 + a_r;
                ldsm_x4s(af[mt][0], af[mt][1], af[mt][2], af[mt][3],
                         Ab + swz128((unsigned)(row*128 + ks*32 + a_cc*16)));
            }
#pragma unroll
            for (int ntp = 0; ntp < 2; ntp++) {
                const int row = wn*32 + ntp*16 + sel_n*8 + r8;
                ldsm_x4s(bf[2*ntp][0], bf[2*ntp][1], bf[2*ntp+1][0], bf[2*ntp+1][1],
                         Bbp + swz128((unsigned)(row*128 + ks*32 + sel_k*16)));
            }
#pragma unroll
            for (int mt = 0; mt < 4; mt++)
#pragma unroll
                for (int nt = 0; nt < 4; nt++)
                    mma16816(acc[mt][nt][0], acc[mt][nt][1], acc[mt][nt][2], acc[mt][nt][3],
                             af[mt][0], af[mt][1], af[mt][2], af[mt][3],
                             bf[nt][0], bf[nt][1]);
        }
    }

#pragma unroll
    for (int mt = 0; mt < 4; mt++) {
#pragma unroll
        for (int nt = 0; nt < 4; nt++) {
            const int row = bm + wm*64 + mt*16 + g;
            const int col = bn + wn*32 + nt*8 + t2;
#pragma unroll
            for (int hm = 0; hm < 2; hm++) {
                const int m = row + hm*8;
                const float v0 = acc[mt][nt][hm*2 + 0] + bias[col];
                const float v1 = acc[mt][nt][hm*2 + 1] + bias[col + 1];
                if (MODE == 0) {
                    __half* dst = (__half*)dst_;
                    const int b = m >> 11, s = m & 2047;
                    const int h = col >> 6, d = col & 63;
                    *(__half2*)&dst[(((size_t)(b*Hh + h))*Ss + s)*Dd + d] =
                        __floats2half2_rn(v0*scale, v1*scale);
                } else {
                    float* dst = (float*)dst_;
                    *(float2*)&dst[(size_t)m * Ee + col] = make_float2(v0, v1);
                }
            }
        }
    }
}

// ============================================================================
// Fused attention (round-11 best: fp32-accum QK, f16x2 exp pass-1,
// 4-slot pass-1 K ring, 3-slot pass-2 rings, evict-first attn stores)
// ============================================================================
#define CH 64
#define NCH (Ss/CH)
#define SLOT (64*72)
#define ATTN_SMEM (6*SLOT*2)

__global__ __launch_bounds__(128, 4)
void attn_kernel(const __half* __restrict__ Qh, const __half* __restrict__ Kh,
                 const __half* __restrict__ Vh, float* __restrict__ attn,
                 __half* __restrict__ ctx)
{
    extern __shared__ __align__(16) __half sh[];

    const int bh = blockIdx.y;
    const int bm = blockIdx.x * 64;
    const __half* Qb = Qh + (size_t)bh * Ss * Dd;
    const __half* Kb = Kh + (size_t)bh * Ss * Dd;
    const __half* Vb = Vh + (size_t)bh * Ss * Dd;
    float* Ob = attn + (size_t)bh * Ss * Ss;

    const int tid = threadIdx.x;
    const int warp = tid >> 5;
    const int lane = tid & 31;
    const int g  = lane >> 2;
    const int t2 = (lane & 3) * 2;
    const int rw = warp * 16;
    const int r8    = lane & 7;
    const int sel_k = (lane >> 3) & 1;
    const int sel_n = (lane >> 4) & 1;

    auto load_k = [&](int kt, int p) {
#pragma unroll
        for (int i = 0; i < 4; i++) {
            const int idx = tid + 128*i;
            const int r = idx >> 3, c8 = (idx & 7) * 8;
            cp16(&sh[p*SLOT + r*72 + c8], Kb + (size_t)(kt*CH + r)*Dd + c8);
        }
    };
    auto load_v = [&](int kt, int p) {
#pragma unroll
        for (int i = 0; i < 4; i++) {
            const int idx = tid + 128*i;
            const int r = idx >> 3, c8 = (idx & 7) * 8;
            cp16(&sh[(3+p)*SLOT + r*72 + c8], Vb + (size_t)(kt*CH + r)*Dd + c8);
        }
    };

#pragma unroll
    for (int i = 0; i < 4; i++) {
        const int idx = tid + 128*i;
        const int r = idx >> 3, c8 = (idx & 7) * 8;
        cp16(&sh[5*SLOT + r*72 + c8], Qb + (size_t)(bm + r)*Dd + c8);
    }
    cp_commit();
    load_k(0, 0); cp_commit();
    load_k(1, 1); cp_commit();
    load_k(2, 2); cp_commit();

    cp_wait<3>();
    __syncthreads();
    unsigned af_q[4][4];
    {
        const int qr = rw + (lane & 15);
        const int qc = ((lane >> 4) & 1) * 8;
#pragma unroll
        for (int kc = 0; kc < 4; kc++)
            ldsm_x4(af_q[kc][0], af_q[kc][1], af_q[kc][2], af_q[kc][3],
                    &sh[5*SLOT + qr*72 + kc*16 + qc]);
    }

    auto qk_chunk = [&](const __half* Kt, float (&acc)[8][4]) {
#pragma unroll
        for (int nt = 0; nt < 8; nt++)
            acc[nt][0] = acc[nt][1] = acc[nt][2] = acc[nt][3] = 0.f;
#pragma unroll
        for (int kc = 0; kc < 4; kc++) {
#pragma unroll
            for (int ntp = 0; ntp < 4; ntp++) {
                unsigned b0, b1, b2, b3;
                ldsm_x4(b0, b1, b2, b3,
                        Kt + (ntp*16 + sel_n*8 + r8)*72 + kc*16 + sel_k*8);
                mma16816(acc[2*ntp][0], acc[2*ntp][1], acc[2*ntp][2], acc[2*ntp][3],
                         af_q[kc][0], af_q[kc][1], af_q[kc][2], af_q[kc][3], b0, b1);
                mma16816(acc[2*ntp+1][0], acc[2*ntp+1][1], acc[2*ntp+1][2], acc[2*ntp+1][3],
                         af_q[kc][0], af_q[kc][1], af_q[kc][2], af_q[kc][3], b2, b3);
            }
        }
    };

    float lsum0 = 0.f, lsum1 = 0.f;
    float acc[8][4];

    // pass 1: row sums via f16x2 ex2
    for (int kt = 0; kt < NCH; kt++) {
        if      (kt + 2 < NCH) cp_wait<2>();
        else if (kt + 1 < NCH) cp_wait<1>();
        else                   cp_wait<0>();
        __syncthreads();
        if (kt + 3 < NCH) { load_k(kt + 3, (kt + 3) & 3); cp_commit(); }

        qk_chunk(&sh[(kt & 3)*SLOT], acc);

#pragma unroll
        for (int nt = 0; nt < 8; nt++) {
            unsigned e01 = h2ex2(f2h2(acc[nt][0], acc[nt][1]));
            unsigned e23 = h2ex2(f2h2(acc[nt][2], acc[nt][3]));
            float2 f01 = __half22float2(*(__half2*)&e01);
            float2 f23 = __half22float2(*(__half2*)&e23);
            lsum0 += f01.x + f01.y;
            lsum1 += f23.x + f23.y;
        }
    }
    lsum0 += __shfl_xor_sync(0xffffffffu, lsum0, 1);
    lsum0 += __shfl_xor_sync(0xffffffffu, lsum0, 2);
    lsum1 += __shfl_xor_sync(0xffffffffu, lsum1, 1);
    lsum1 += __shfl_xor_sync(0xffffffffu, lsum1, 2);
    const float inv0 = 1.0f / lsum0;
    const float inv1 = 1.0f / lsum1;

    __syncthreads();

    // pass 2: write attn + P·V
    float cacc[8][4];
#pragma unroll
    for (int dt = 0; dt < 8; dt++)
        cacc[dt][0] = cacc[dt][1] = cacc[dt][2] = cacc[dt][3] = 0.f;

    load_k(0, 0); load_v(0, 0); cp_commit();
    load_k(1, 1); load_v(1, 1); cp_commit();

    for (int kt = 0; kt < NCH; kt++) {
        if (kt + 1 < NCH) cp_wait<1>(); else cp_wait<0>();
        __syncthreads();
        if (kt + 2 < NCH) {
            load_k(kt + 2, (kt + 2) % 3);
            load_v(kt + 2, (kt + 2) % 3);
            cp_commit();
        }

        const __half* Kt = &sh[(kt % 3)*SLOT];
        const __half* Vt = &sh[(3 + kt % 3)*SLOT];

        qk_chunk(Kt, acc);

        const int row0 = bm + rw + g;
#pragma unroll
        for (int nt = 0; nt < 8; nt++) {
            const float p0 = ex2f(acc[nt][0]) * inv0;
            const float p1 = ex2f(acc[nt][1]) * inv0;
            const float p2 = ex2f(acc[nt][2]) * inv1;
            const float p3 = ex2f(acc[nt][3]) * inv1;
            const int col = kt*CH + nt*8 + t2;
            stg_cs_v2(Ob + (size_t)row0 * Ss + col, p0, p1);
            stg_cs_v2(Ob + (size_t)(row0 + 8) * Ss + col, p2, p3);
            acc[nt][0] = p0; acc[nt][1] = p1; acc[nt][2] = p2; acc[nt][3] = p3;
        }

#pragma unroll
        for (int kc2 = 0; kc2 < 4; kc2++) {
            const unsigned pa0 = f2h2(acc[2*kc2    ][0], acc[2*kc2    ][1]);
            const unsigned pa1 = f2h2(acc[2*kc2    ][2], acc[2*kc2    ][3]);
            const unsigned pa2 = f2h2(acc[2*kc2 + 1][0], acc[2*kc2 + 1][1]);
            const unsigned pa3 = f2h2(acc[2*kc2 + 1][2], acc[2*kc2 + 1][3]);
#pragma unroll
            for (int dtp = 0; dtp < 4; dtp++) {
                unsigned b0, b1, b2, b3;
                ldsm_x4t(b0, b1, b2, b3,
                         Vt + (kc2*16 + sel_k*8 + r8)*72 + (dtp*2 + sel_n)*8);
                mma16816(cacc[2*dtp][0], cacc[2*dtp][1], cacc[2*dtp][2], cacc[2*dtp][3],
                         pa0, pa1, pa2, pa3, b0, b1);
                mma16816(cacc[2*dtp+1][0], cacc[2*dtp+1][1], cacc[2*dtp+1][2], cacc[2*dtp+1][3],
                         pa0, pa1, pa2, pa3, b2, b3);
            }
        }
    }

    // epilogue: ctx (fp16)
    const int b = bh >> 4;
    const int h = bh & 15;
    const int s0 = bm + rw + g;
#pragma unroll
    for (int dt = 0; dt < 8; dt++) {
        const int d = dt*8 + t2;
        *(__half2*)(ctx + ((size_t)b * Ss + s0    ) * Ee + h*Dd + d) =
            __floats2half2_rn(cacc[dt][0], cacc[dt][1]);
        *(__half2*)(ctx + ((size_t)b * Ss + s0 + 8) * Ee + h*Dd + d) =
            __floats2half2_rn(cacc[dt][2], cacc[dt][3]);
    }
}

// ============================================================================
extern "C" void kernel_launch(void* const* d_in, const int* in_sizes, int n_in,
                              void* d_out, int out_size)
{
    const float* query  = (const float*)d_in[0];
    const float* key_in = (const float*)d_in[1];
    const float* value  = (const float*)d_in[2];
    const float* Wq = (const float*)d_in[3];
    const float* bq = (const float*)d_in[4];
    const float* Wk = (const float*)d_in[5];
    const float* bk = (const float*)d_in[6];
    const float* Wv = (const float*)d_in[7];
    const float* bv = (const float*)d_in[8];
    const float* Wo = (const float*)d_in[9];
    const float* bo = (const float*)d_in[10];

    float* out = (float*)d_out;

    __half *xq, *xk, *xv, *wq, *wk, *wv, *wo, *Qh, *Kh, *Vh, *ctxh;
    float *attn;
    cudaGetSymbolAddress((void**)&xq, g_xq);
    cudaGetSymbolAddress((void**)&xk, g_xk);
    cudaGetSymbolAddress((void**)&xv, g_xv);
    cudaGetSymbolAddress((void**)&wq, g_wq);
    cudaGetSymbolAddress((void**)&wk, g_wk);
    cudaGetSymbolAddress((void**)&wv, g_wv);
    cudaGetSymbolAddress((void**)&wo, g_wo);
    cudaGetSymbolAddress((void**)&Qh, g_Qh);
    cudaGetSymbolAddress((void**)&Kh, g_Kh);
    cudaGetSymbolAddress((void**)&Vh, g_Vh);
    cudaGetSymbolAddress((void**)&ctxh, g_ctxh);

    const size_t BSE = (size_t)Bb * Ss * Ee;
    if ((size_t)out_size > BSE) {
        attn = out + BSE;
    } else {
        cudaGetSymbolAddress((void**)&attn, g_attn_fb);
    }

    cudaFuncSetAttribute(attn_kernel,
                         cudaFuncAttributeMaxDynamicSharedMemorySize, ATTN_SMEM);
    cudaFuncSetAttribute(proj16_kernel<0>,
                         cudaFuncAttributeMaxDynamicSharedMemorySize, PROJ_SMEM);
    cudaFuncSetAttribute(proj16_kernel<1>,
                         cudaFuncAttributeMaxDynamicSharedMemorySize, PROJ_SMEM);

    f2h_all_kernel<<<3*IN_BLK + 4*W_BLK, 256>>>(query, key_in, value, Wq, Wk, Wv, Wo,
                                                xq, xk, xv, wq, wk, wv, wo);

    proj16_kernel<0><<<dim3(Ee/128, MTOK/128, 3), 256, PROJ_SMEM>>>(
        xq, xk, xv, wq, wk, wv, bq, bk, bv, Qh, Kh, Vh);

    attn_kernel<<<dim3(Ss/64, BH), 128, ATTN_SMEM>>>(Qh, Kh, Vh, attn, ctxh);

    proj16_kernel<1><<<dim3(Ee/128, MTOK/128, 1), 256, PROJ_SMEM>>>(
        ctxh, nullptr, nullptr, wo, nullptr, nullptr,
        bo, nullptr, nullptr, out, nullptr, nullptr);
}

// round 14
// speedup vs baseline: 1.0971x; 1.0971x over previous
#include <cuda_runtime.h>
#include <cuda_fp16.h>
#include <math.h>

#define Bb 4
#define Ss 2048
#define Ee 1024
#define Hh 16
#define Dd 64
#define MTOK (Bb*Ss)
#define BH   (Bb*Hh)

#define QSCALE 0.1803368801111204f   // 0.125 * log2(e)

// ---------------- scratch ----------------
__device__ __half g_xq[(size_t)MTOK*Ee];
__device__ __half g_xk[(size_t)MTOK*Ee];
__device__ __half g_xv[(size_t)MTOK*Ee];
__device__ __half g_wq[(size_t)Ee*Ee];
__device__ __half g_wk[(size_t)Ee*Ee];
__device__ __half g_wv[(size_t)Ee*Ee];
__device__ __half g_wo[(size_t)Ee*Ee];
__device__ __half g_Qh[(size_t)BH*Ss*Dd];
__device__ __half g_Kh[(size_t)BH*Ss*Dd];
__device__ __half g_Vh[(size_t)BH*Ss*Dd];
__device__ __half g_ctxh[(size_t)Bb*Ss*Ee];
__device__ float  g_attn_fb[(size_t)BH*Ss*Ss];

__device__ __forceinline__ void mma16816(float& c0, float& c1, float& c2, float& c3,
                                         unsigned a0, unsigned a1, unsigned a2, unsigned a3,
                                         unsigned b0, unsigned b1)
{
    asm volatile(
        "mma.sync.aligned.m16n8k16.row.col.f32.f16.f16.f32 "
        "{%0,%1,%2,%3}, {%4,%5,%6,%7}, {%8,%9}, {%0,%1,%2,%3};\n"
        : "+f"(c0), "+f"(c1), "+f"(c2), "+f"(c3)
        : "r"(a0), "r"(a1), "r"(a2), "r"(a3), "r"(b0), "r"(b1));
}
__device__ __forceinline__ unsigned f2h2(float a, float b) {
    __half2 h = __floats2half2_rn(a, b);
    return *(unsigned*)&h;
}
__device__ __forceinline__ float ex2f(float x) {
    float y; asm("ex2.approx.f32 %0, %1;" : "=f"(y) : "f"(x)); return y;
}
__device__ __forceinline__ unsigned h2ex2(unsigned x) {
    unsigned y; asm("ex2.approx.f16x2 %0, %1;" : "=r"(y) : "r"(x)); return y;
}
__device__ __forceinline__ void cp16(void* smem, const void* gmem) {
    unsigned s = (unsigned)__cvta_generic_to_shared(smem);
    asm volatile("cp.async.cg.shared.global [%0], [%1], 16;" :: "r"(s), "l"(gmem));
}
__device__ __forceinline__ void cp_commit() { asm volatile("cp.async.commit_group;"); }
template<int N> __device__ __forceinline__ void cp_wait() {
    asm volatile("cp.async.wait_group %0;" :: "n"(N));
}
__device__ __forceinline__ void ldsm_x4(unsigned& r0, unsigned& r1, unsigned& r2, unsigned& r3,
                                        const __half* p) {
    unsigned s = (unsigned)__cvta_generic_to_shared(p);
    asm volatile("ldmatrix.sync.aligned.m8n8.x4.shared.b16 {%0,%1,%2,%3}, [%4];"
        : "=r"(r0), "=r"(r1), "=r"(r2), "=r"(r3) : "r"(s));
}
__device__ __forceinline__ void ldsm_x4t(unsigned& r0, unsigned& r1, unsigned& r2, unsigned& r3,
                                         const __half* p) {
    unsigned s = (unsigned)__cvta_generic_to_shared(p);
    asm volatile("ldmatrix.sync.aligned.m8n8.x4.trans.shared.b16 {%0,%1,%2,%3}, [%4];"
        : "=r"(r0), "=r"(r1), "=r"(r2), "=r"(r3) : "r"(s));
}
__device__ __forceinline__ void stg_cs_v2(float* p, float a, float b) {
    asm volatile("st.global.cs.v2.f32 [%0], {%1, %2};" :: "l"(p), "f"(a), "f"(b) : "memory");
}
__device__ __forceinline__ unsigned swz64(unsigned x) { return x ^ ((x >> 3) & 0x30u); }

// ============================================================================
// fused fp32->fp16 conversion of all inputs + weights
// ============================================================================
#define IN4 ((int)((size_t)MTOK*Ee/4))
#define W4  ((int)((size_t)Ee*Ee/4))
#define IN_BLK (IN4/256)
#define W_BLK  (W4/256)

__global__ __launch_bounds__(256)
void f2h_all_kernel(const float* __restrict__ q, const float* __restrict__ k,
                    const float* __restrict__ v, const float* __restrict__ wq,
                    const float* __restrict__ wk, const float* __restrict__ wv,
                    const float* __restrict__ wo,
                    __half* xq, __half* xk, __half* xv,
                    __half* hq, __half* hk, __half* hv, __half* ho)
{
    int blk = blockIdx.x;
    const float* src; __half* dst;
    if      (blk < 1*IN_BLK)          { src = q;  dst = xq; blk -= 0; }
    else if (blk < 2*IN_BLK)          { src = k;  dst = xk; blk -= 1*IN_BLK; }
    else if (blk < 3*IN_BLK)          { src = v;  dst = xv; blk -= 2*IN_BLK; }
    else if (blk < 3*IN_BLK + W_BLK)  { src = wq; dst = hq; blk -= 3*IN_BLK; }
    else if (blk < 3*IN_BLK + 2*W_BLK){ src = wk; dst = hk; blk -= 3*IN_BLK + W_BLK; }
    else if (blk < 3*IN_BLK + 3*W_BLK){ src = wv; dst = hv; blk -= 3*IN_BLK + 2*W_BLK; }
    else                              { src = wo; dst = ho; blk -= 3*IN_BLK + 3*W_BLK; }
    const int i = blk * 256 + threadIdx.x;
    float4 val = ((const float4*)src)[i];
    ((__half2*)dst)[2*i]     = __floats2half2_rn(val.x, val.y);
    ((__half2*)dst)[2*i + 1] = __floats2half2_rn(val.z, val.w);
}

// ============================================================================
// proj16 (round-8 proven): BK=32, SW64, 3-stage, static 48KB smem, 2 CTA/SM
// ============================================================================
#define PSTG 8192

template<int MODE>
__global__ __launch_bounds__(256)
void proj16_kernel(const __half* __restrict__ A0, const __half* __restrict__ A1,
                   const __half* __restrict__ A2,
                   const __half* __restrict__ W0, const __half* __restrict__ W1,
                   const __half* __restrict__ W2,
                   const float* __restrict__ b0p, const float* __restrict__ b1p,
                   const float* __restrict__ b2p,
                   void* d0, void* d1, void* d2)
{
    __shared__ __align__(128) unsigned char smA[3*PSTG];
    __shared__ __align__(128) unsigned char smB[3*PSTG];

    const __half* A; const __half* W; const float* bias; void* dst_; float scale;
    if (MODE == 0) {
        const int z = blockIdx.z;
        if (z == 0)      { A = A0; W = W0; bias = b0p; dst_ = d0; scale = QSCALE; }
        else if (z == 1) { A = A1; W = W1; bias = b1p; dst_ = d1; scale = 1.0f; }
        else             { A = A2; W = W2; bias = b2p; dst_ = d2; scale = 1.0f; }
    } else {
        A = A0; W = W0; bias = b0p; dst_ = d0; scale = 1.0f;
    }

    const int bm = blockIdx.y * 128;
    const int bn = blockIdx.x * 128;
    const int tid = threadIdx.x;
    const int warp = tid >> 5;
    const int lane = tid & 31;
    const int wm = warp >> 2;
    const int wn = warp & 3;
    const int g  = lane >> 2;
    const int t2 = (lane & 3) * 2;
    const int a_r  = lane & 15;
    const int a_cc = (lane >> 4) & 1;
    const int r8    = lane & 7;
    const int sel_k = (lane >> 3) & 1;
    const int sel_n = (lane >> 4) & 1;

    float acc[4][4][4] = {};

    auto stage = [&](int kt, int s) {
        const int k0 = kt * 32;
#pragma unroll
        for (int i = 0; i < 2; i++) {
            const int idx = tid + 256*i;
            const int r = idx >> 2, c = idx & 3;
            const unsigned off = swz64((unsigned)(r*64 + c*16));
            cp16(smA + s*PSTG + off, A + (size_t)(bm + r) * Ee + k0 + c*8);
            cp16(smB + s*PSTG + off, W + (size_t)(bn + r) * Ee + k0 + c*8);
        }
    };

    const int NK = Ee/32;
    stage(0, 0); cp_commit();
    stage(1, 1); cp_commit();

    for (int kt = 0; kt < NK; kt++) {
        if (kt + 1 < NK) cp_wait<1>(); else cp_wait<0>();
        __syncthreads();
        if (kt + 2 < NK) { stage(kt + 2, (kt + 2) % 3); cp_commit(); }

        const unsigned char* Ab = smA + (kt % 3) * PSTG;
        const unsigned char* Bbp = smB + (kt % 3) * PSTG;

#pragma unroll
        for (int ks = 0; ks < 2; ks++) {
            const int ck = ks * 2;
            unsigned af[4][4], bf[4][2];
#pragma unroll
            for (int mt = 0; mt < 4; mt++) {
                const int row = wm*64 + mt*16 + a_r;
                ldsm_x4(af[mt][0], af[mt][1], af[mt][2], af[mt][3],
                        (const __half*)(Ab + swz64((unsigned)(row*64 + (ck + a_cc)*16))));
            }
#pragma unroll
            for (int ntp = 0; ntp < 2; ntp++) {
                const int row = wn*32 + ntp*16 + sel_n*8 + r8;
                ldsm_x4(bf[2*ntp][0], bf[2*ntp][1], bf[2*ntp+1][0], bf[2*ntp+1][1],
                        (const __half*)(Bbp + swz64((unsigned)(row*64 + (ck + sel_k)*16))));
            }
#pragma unroll
            for (int mt = 0; mt < 4; mt++)
#pragma unroll
                for (int nt = 0; nt < 4; nt++)
                    mma16816(acc[mt][nt][0], acc[mt][nt][1], acc[mt][nt][2], acc[mt][nt][3],
                             af[mt][0], af[mt][1], af[mt][2], af[mt][3],
                             bf[nt][0], bf[nt][1]);
        }
    }

#pragma unroll
    for (int mt = 0; mt < 4; mt++) {
#pragma unroll
        for (int nt = 0; nt < 4; nt++) {
            const int row = bm + wm*64 + mt*16 + g;
            const int col = bn + wn*32 + nt*8 + t2;
#pragma unroll
            for (int hm = 0; hm < 2; hm++) {
                const int m = row + hm*8;
                const float v0 = acc[mt][nt][hm*2 + 0] + bias[col];
                const float v1 = acc[mt][nt][hm*2 + 1] + bias[col + 1];
                if (MODE == 0) {
                    __half* dst = (__half*)dst_;
                    const int b = m >> 11, s = m & 2047;
                    const int h = col >> 6, d = col & 63;
                    *(__half2*)&dst[(((size_t)(b*Hh + h))*Ss + s)*Dd + d] =
                        __floats2half2_rn(v0*scale, v1*scale);
                } else {
                    float* dst = (float*)dst_;
                    *(float2*)&dst[(size_t)m * Ee + col] = make_float2(v0, v1);
                }
            }
        }
    }
}

// ============================================================================
// Fused attention: 128 thr / 128 q-rows per CTA (warp = 32 rows, 2 m-tiles
// share every K/V fragment -> LDS per mma halved). 2 CTAs/SM.
// Pass 1: 4-slot K ring, f16x2 exp row sums. Pass 2: 3+3 rings, fp32 exp,
// evict-first attn stores, fp32-accum P·V.
// ============================================================================
#define CH 64
#define NCH (Ss/CH)
#define SLOT (64*72)
#define ATTN_SMEM (6*SLOT*2)         // 55,296 B (Q staged in slots 4-5)

__global__ __launch_bounds__(128, 2)
void attn_kernel(const __half* __restrict__ Qh, const __half* __restrict__ Kh,
                 const __half* __restrict__ Vh, float* __restrict__ attn,
                 __half* __restrict__ ctx)
{
    extern __shared__ __align__(16) __half sh[];

    const int bh = blockIdx.y;
    const int bm = blockIdx.x * 128;
    const __half* Qb = Qh + (size_t)bh * Ss * Dd;
    const __half* Kb = Kh + (size_t)bh * Ss * Dd;
    const __half* Vb = Vh + (size_t)bh * Ss * Dd;
    float* Ob = attn + (size_t)bh * Ss * Ss;

    const int tid = threadIdx.x;
    const int warp = tid >> 5;
    const int lane = tid & 31;
    const int g  = lane >> 2;
    const int t2 = (lane & 3) * 2;
    const int rw = warp * 32;            // warp covers 32 q-rows (2 m-tiles)
    const int r8    = lane & 7;
    const int sel_k = (lane >> 3) & 1;
    const int sel_n = (lane >> 4) & 1;

    auto load_k = [&](int kt, int p) {
#pragma unroll
        for (int i = 0; i < 4; i++) {
            const int idx = tid + 128*i;
            const int r = idx >> 3, c8 = (idx & 7) * 8;
            cp16(&sh[p*SLOT + r*72 + c8], Kb + (size_t)(kt*CH + r)*Dd + c8);
        }
    };
    auto load_v = [&](int kt, int p) {
#pragma unroll
        for (int i = 0; i < 4; i++) {
            const int idx = tid + 128*i;
            const int r = idx >> 3, c8 = (idx & 7) * 8;
            cp16(&sh[(3+p)*SLOT + r*72 + c8], Vb + (size_t)(kt*CH + r)*Dd + c8);
        }
    };

    // ---- stage Q (128 rows) into slots 4-5 ----
#pragma unroll
    for (int i = 0; i < 8; i++) {
        const int idx = tid + 128*i;               // 0..1023
        const int r = idx >> 3, c8 = (idx & 7) * 8;
        cp16(&sh[4*SLOT + r*72 + c8], Qb + (size_t)(bm + r)*Dd + c8);
    }
    cp_commit();
    load_k(0, 0); cp_commit();
    load_k(1, 1); cp_commit();
    load_k(2, 2); cp_commit();

    cp_wait<3>();
    __syncthreads();
    unsigned af_q[2][4][4];
    {
        const int qc = ((lane >> 4) & 1) * 8;
#pragma unroll
        for (int m = 0; m < 2; m++) {
            const int qr = rw + m*16 + (lane & 15);
#pragma unroll
            for (int kc = 0; kc < 4; kc++)
                ldsm_x4(af_q[m][kc][0], af_q[m][kc][1], af_q[m][kc][2], af_q[m][kc][3],
                        &sh[4*SLOT + qr*72 + kc*16 + qc]);
        }
    }

    // QK for one 64-key chunk: B fragments shared across the 2 m-tiles
    auto qk_chunk = [&](const __half* Kt, float (&acc)[2][8][4]) {
#pragma unroll
        for (int m = 0; m < 2; m++)
#pragma unroll
            for (int nt = 0; nt < 8; nt++)
                acc[m][nt][0] = acc[m][nt][1] = acc[m][nt][2] = acc[m][nt][3] = 0.f;
#pragma unroll
        for (int kc = 0; kc < 4; kc++) {
#pragma unroll
            for (int ntp = 0; ntp < 4; ntp++) {
                unsigned b0, b1, b2, b3;
                ldsm_x4(b0, b1, b2, b3,
                        Kt + (ntp*16 + sel_n*8 + r8)*72 + kc*16 + sel_k*8);
#pragma unroll
                for (int m = 0; m < 2; m++) {
                    mma16816(acc[m][2*ntp][0], acc[m][2*ntp][1],
                             acc[m][2*ntp][2], acc[m][2*ntp][3],
                             af_q[m][kc][0], af_q[m][kc][1],
                             af_q[m][kc][2], af_q[m][kc][3], b0, b1);
                    mma16816(acc[m][2*ntp+1][0], acc[m][2*ntp+1][1],
                             acc[m][2*ntp+1][2], acc[m][2*ntp+1][3],
                             af_q[m][kc][0], af_q[m][kc][1],
                             af_q[m][kc][2], af_q[m][kc][3], b2, b3);
                }
            }
        }
    };

    float lsum[2][2] = {};
    float acc[2][8][4];

    // =================== pass 1: row sums via f16x2 ex2 ===================
    for (int kt = 0; kt < NCH; kt++) {
        if      (kt + 2 < NCH) cp_wait<2>();
        else if (kt + 1 < NCH) cp_wait<1>();
        else                   cp_wait<0>();
        __syncthreads();
        if (kt + 3 < NCH) { load_k(kt + 3, (kt + 3) & 3); cp_commit(); }

        qk_chunk(&sh[(kt & 3)*SLOT], acc);

#pragma unroll
        for (int m = 0; m < 2; m++)
#pragma unroll
            for (int nt = 0; nt < 8; nt++) {
                unsigned e01 = h2ex2(f2h2(acc[m][nt][0], acc[m][nt][1]));
                unsigned e23 = h2ex2(f2h2(acc[m][nt][2], acc[m][nt][3]));
                float2 f01 = __half22float2(*(__half2*)&e01);
                float2 f23 = __half22float2(*(__half2*)&e23);
                lsum[m][0] += f01.x + f01.y;
                lsum[m][1] += f23.x + f23.y;
            }
    }
    float inv[2][2];
#pragma unroll
    for (int m = 0; m < 2; m++)
#pragma unroll
        for (int hrow = 0; hrow < 2; hrow++) {
            float s = lsum[m][hrow];
            s += __shfl_xor_sync(0xffffffffu, s, 1);
            s += __shfl_xor_sync(0xffffffffu, s, 2);
            inv[m][hrow] = 1.0f / s;
        }

    __syncthreads();

    // =================== pass 2: write attn + P·V ===================
    float cacc[2][8][4];
#pragma unroll
    for (int m = 0; m < 2; m++)
#pragma unroll
        for (int dt = 0; dt < 8; dt++)
            cacc[m][dt][0] = cacc[m][dt][1] = cacc[m][dt][2] = cacc[m][dt][3] = 0.f;

    load_k(0, 0); load_v(0, 0); cp_commit();
    load_k(1, 1); load_v(1, 1); cp_commit();

    for (int kt = 0; kt < NCH; kt++) {
        if (kt + 1 < NCH) cp_wait<1>(); else cp_wait<0>();
        __syncthreads();
        if (kt + 2 < NCH) {
            load_k(kt + 2, (kt + 2) % 3);
            load_v(kt + 2, (kt + 2) % 3);
            cp_commit();
        }

        const __half* Kt = &sh[(kt % 3)*SLOT];
        const __half* Vt = &sh[(3 + kt % 3)*SLOT];

        qk_chunk(Kt, acc);

#pragma unroll
        for (int m = 0; m < 2; m++) {
            const int row0 = bm + rw + m*16 + g;
#pragma unroll
            for (int nt = 0; nt < 8; nt++) {
                const float p0 = ex2f(acc[m][nt][0]) * inv[m][0];
                const float p1 = ex2f(acc[m][nt][1]) * inv[m][0];
                const float p2 = ex2f(acc[m][nt][2]) * inv[m][1];
                const float p3 = ex2f(acc[m][nt][3]) * inv[m][1];
                const int col = kt*CH + nt*8 + t2;
                stg_cs_v2(Ob + (size_t)row0 * Ss + col, p0, p1);
                stg_cs_v2(Ob + (size_t)(row0 + 8) * Ss + col, p2, p3);
                acc[m][nt][0] = p0; acc[m][nt][1] = p1;
                acc[m][nt][2] = p2; acc[m][nt][3] = p3;
            }
        }

        // P·V: V fragments shared across both m-tiles
#pragma unroll
        for (int kc2 = 0; kc2 < 4; kc2++) {
            unsigned pa[2][4];
#pragma unroll
            for (int m = 0; m < 2; m++) {
                pa[m][0] = f2h2(acc[m][2*kc2    ][0], acc[m][2*kc2    ][1]);
                pa[m][1] = f2h2(acc[m][2*kc2    ][2], acc[m][2*kc2    ][3]);
                pa[m][2] = f2h2(acc[m][2*kc2 + 1][0], acc[m][2*kc2 + 1][1]);
                pa[m][3] = f2h2(acc[m][2*kc2 + 1][2], acc[m][2*kc2 + 1][3]);
            }
#pragma unroll
            for (int dtp = 0; dtp < 4; dtp++) {
                unsigned b0, b1, b2, b3;
                ldsm_x4t(b0, b1, b2, b3,
                         Vt + (kc2*16 + sel_k*8 + r8)*72 + (dtp*2 + sel_n)*8);
#pragma unroll
                for (int m = 0; m < 2; m++) {
                    mma16816(cacc[m][2*dtp][0], cacc[m][2*dtp][1],
                             cacc[m][2*dtp][2], cacc[m][2*dtp][3],
                             pa[m][0], pa[m][1], pa[m][2], pa[m][3], b0, b1);
                    mma16816(cacc[m][2*dtp+1][0], cacc[m][2*dtp+1][1],
                             cacc[m][2*dtp+1][2], cacc[m][2*dtp+1][3],
                             pa[m][0], pa[m][1], pa[m][2], pa[m][3], b2, b3);
                }
            }
        }
    }

    // ---- epilogue: ctx (fp16) ----
    const int b = bh >> 4;
    const int h = bh & 15;
#pragma unroll
    for (int m = 0; m < 2; m++) {
        const int s0 = bm + rw + m*16 + g;
#pragma unroll
        for (int dt = 0; dt < 8; dt++) {
            const int d = dt*8 + t2;
            *(__half2*)(ctx + ((size_t)b * Ss + s0    ) * Ee + h*Dd + d) =
                __floats2half2_rn(cacc[m][dt][0], cacc[m][dt][1]);
            *(__half2*)(ctx + ((size_t)b * Ss + s0 + 8) * Ee + h*Dd + d) =
                __floats2half2_rn(cacc[m][dt][2], cacc[m][dt][3]);
        }
    }
}

// ============================================================================
extern "C" void kernel_launch(void* const* d_in, const int* in_sizes, int n_in,
                              void* d_out, int out_size)
{
    const float* query  = (const float*)d_in[0];
    const float* key_in = (const float*)d_in[1];
    const float* value  = (const float*)d_in[2];
    const float* Wq = (const float*)d_in[3];
    const float* bq = (const float*)d_in[4];
    const float* Wk = (const float*)d_in[5];
    const float* bk = (const float*)d_in[6];
    const float* Wv = (const float*)d_in[7];
    const float* bv = (const float*)d_in[8];
    const float* Wo = (const float*)d_in[9];
    const float* bo = (const float*)d_in[10];

    float* out = (float*)d_out;

    __half *xq, *xk, *xv, *wq, *wk, *wv, *wo, *Qh, *Kh, *Vh, *ctxh;
    float *attn;
    cudaGetSymbolAddress((void**)&xq, g_xq);
    cudaGetSymbolAddress((void**)&xk, g_xk);
    cudaGetSymbolAddress((void**)&xv, g_xv);
    cudaGetSymbolAddress((void**)&wq, g_wq);
    cudaGetSymbolAddress((void**)&wk, g_wk);
    cudaGetSymbolAddress((void**)&wv, g_wv);
    cudaGetSymbolAddress((void**)&wo, g_wo);
    cudaGetSymbolAddress((void**)&Qh, g_Qh);
    cudaGetSymbolAddress((void**)&Kh, g_Kh);
    cudaGetSymbolAddress((void**)&Vh, g_Vh);
    cudaGetSymbolAddress((void**)&ctxh, g_ctxh);

    const size_t BSE = (size_t)Bb * Ss * Ee;
    if ((size_t)out_size > BSE) {
        attn = out + BSE;
    } else {
        cudaGetSymbolAddress((void**)&attn, g_attn_fb);
    }

    cudaFuncSetAttribute(attn_kernel,
                         cudaFuncAttributeMaxDynamicSharedMemorySize, ATTN_SMEM);

    f2h_all_kernel<<<3*IN_BLK + 4*W_BLK, 256>>>(query, key_in, value, Wq, Wk, Wv, Wo,
                                                xq, xk, xv, wq, wk, wv, wo);

    proj16_kernel<0><<<dim3(Ee/128, MTOK/128, 3), 256>>>(
        xq, xk, xv, wq, wk, wv, bq, bk, bv, Qh, Kh, Vh);

    attn_kernel<<<dim3(Ss/128, BH), 128, ATTN_SMEM>>>(Qh, Kh, Vh, attn, ctxh);

    proj16_kernel<1><<<dim3(Ee/128, MTOK/128, 1), 256>>>(
        ctxh, nullptr, nullptr, wo, nullptr, nullptr,
        bo, nullptr, nullptr, out, nullptr, nullptr);
}

// round 15
// speedup vs baseline: 1.1397x; 1.0388x over previous
#include <cuda_runtime.h>
#include <cuda_fp16.h>
#include <math.h>

#define Bb 4
#define Ss 2048
#define Ee 1024
#define Hh 16
#define Dd 64
#define MTOK (Bb*Ss)
#define BH   (Bb*Hh)

#define QSCALE 0.1803368801111204f   // 0.125 * log2(e)

// ---------------- scratch ----------------
__device__ __half g_xq[(size_t)MTOK*Ee];
__device__ __half g_xk[(size_t)MTOK*Ee];
__device__ __half g_xv[(size_t)MTOK*Ee];
__device__ __half g_wq[(size_t)Ee*Ee];
__device__ __half g_wk[(size_t)Ee*Ee];
__device__ __half g_wv[(size_t)Ee*Ee];
__device__ __half g_wo[(size_t)Ee*Ee];
__device__ __half g_Qh[(size_t)BH*Ss*Dd];
__device__ __half g_Kh[(size_t)BH*Ss*Dd];
__device__ __half g_Vh[(size_t)BH*Ss*Dd];
__device__ __half g_ctxh[(size_t)Bb*Ss*Ee];
__device__ float  g_attn_fb[(size_t)BH*Ss*Ss];

__device__ __forceinline__ void mma16816(float& c0, float& c1, float& c2, float& c3,
                                         unsigned a0, unsigned a1, unsigned a2, unsigned a3,
                                         unsigned b0, unsigned b1)
{
    asm volatile(
        "mma.sync.aligned.m16n8k16.row.col.f32.f16.f16.f32 "
        "{%0,%1,%2,%3}, {%4,%5,%6,%7}, {%8,%9}, {%0,%1,%2,%3};\n"
        : "+f"(c0), "+f"(c1), "+f"(c2), "+f"(c3)
        : "r"(a0), "r"(a1), "r"(a2), "r"(a3), "r"(b0), "r"(b1));
}
__device__ __forceinline__ unsigned f2h2(float a, float b) {
    __half2 h = __floats2half2_rn(a, b);
    return *(unsigned*)&h;
}
__device__ __forceinline__ float ex2f(float x) {
    float y; asm("ex2.approx.f32 %0, %1;" : "=f"(y) : "f"(x)); return y;
}
__device__ __forceinline__ unsigned h2ex2(unsigned x) {
    unsigned y; asm("ex2.approx.f16x2 %0, %1;" : "=r"(y) : "r"(x)); return y;
}
__device__ __forceinline__ void cp16(void* smem, const void* gmem) {
    unsigned s = (unsigned)__cvta_generic_to_shared(smem);
    asm volatile("cp.async.cg.shared.global [%0], [%1], 16;" :: "r"(s), "l"(gmem));
}
__device__ __forceinline__ void cp_commit() { asm volatile("cp.async.commit_group;"); }
template<int N> __device__ __forceinline__ void cp_wait() {
    asm volatile("cp.async.wait_group %0;" :: "n"(N));
}
__device__ __forceinline__ void ldsm_x4(unsigned& r0, unsigned& r1, unsigned& r2, unsigned& r3,
                                        const __half* p) {
    unsigned s = (unsigned)__cvta_generic_to_shared(p);
    asm volatile("ldmatrix.sync.aligned.m8n8.x4.shared.b16 {%0,%1,%2,%3}, [%4];"
        : "=r"(r0), "=r"(r1), "=r"(r2), "=r"(r3) : "r"(s));
}
__device__ __forceinline__ void ldsm_x4t(unsigned& r0, unsigned& r1, unsigned& r2, unsigned& r3,
                                         const __half* p) {
    unsigned s = (unsigned)__cvta_generic_to_shared(p);
    asm volatile("ldmatrix.sync.aligned.m8n8.x4.trans.shared.b16 {%0,%1,%2,%3}, [%4];"
        : "=r"(r0), "=r"(r1), "=r"(r2), "=r"(r3) : "r"(s));
}
__device__ __forceinline__ void stg_cs_v2(float* p, float a, float b) {
    asm volatile("st.global.cs.v2.f32 [%0], {%1, %2};" :: "l"(p), "f"(a), "f"(b) : "memory");
}
__device__ __forceinline__ unsigned swz64(unsigned x) { return x ^ ((x >> 3) & 0x30u); }

// ============================================================================
// fused fp32->fp16 conversion of all inputs + weights
// ============================================================================
#define IN4 ((int)((size_t)MTOK*Ee/4))
#define W4  ((int)((size_t)Ee*Ee/4))
#define IN_BLK (IN4/256)
#define W_BLK  (W4/256)

__global__ __launch_bounds__(256)
void f2h_all_kernel(const float* __restrict__ q, const float* __restrict__ k,
                    const float* __restrict__ v, const float* __restrict__ wq,
                    const float* __restrict__ wk, const float* __restrict__ wv,
                    const float* __restrict__ wo,
                    __half* xq, __half* xk, __half* xv,
                    __half* hq, __half* hk, __half* hv, __half* ho)
{
    int blk = blockIdx.x;
    const float* src; __half* dst;
    if      (blk < 1*IN_BLK)          { src = q;  dst = xq; blk -= 0; }
    else if (blk < 2*IN_BLK)          { src = k;  dst = xk; blk -= 1*IN_BLK; }
    else if (blk < 3*IN_BLK)          { src = v;  dst = xv; blk -= 2*IN_BLK; }
    else if (blk < 3*IN_BLK + W_BLK)  { src = wq; dst = hq; blk -= 3*IN_BLK; }
    else if (blk < 3*IN_BLK + 2*W_BLK){ src = wk; dst = hk; blk -= 3*IN_BLK + W_BLK; }
    else if (blk < 3*IN_BLK + 3*W_BLK){ src = wv; dst = hv; blk -= 3*IN_BLK + 2*W_BLK; }
    else                              { src = wo; dst = ho; blk -= 3*IN_BLK + 3*W_BLK; }
    const int i = blk * 256 + threadIdx.x;
    float4 val = ((const float4*)src)[i];
    ((__half2*)dst)[2*i]     = __floats2half2_rn(val.x, val.y);
    ((__half2*)dst)[2*i + 1] = __floats2half2_rn(val.z, val.w);
}

// ============================================================================
// proj16 (round-8 proven): BK=32, SW64, 3-stage, static 48KB smem, 2 CTA/SM
// ============================================================================
#define PSTG 8192

template<int MODE>
__global__ __launch_bounds__(256)
void proj16_kernel(const __half* __restrict__ A0, const __half* __restrict__ A1,
                   const __half* __restrict__ A2,
                   const __half* __restrict__ W0, const __half* __restrict__ W1,
                   const __half* __restrict__ W2,
                   const float* __restrict__ b0p, const float* __restrict__ b1p,
                   const float* __restrict__ b2p,
                   void* d0, void* d1, void* d2)
{
    __shared__ __align__(128) unsigned char smA[3*PSTG];
    __shared__ __align__(128) unsigned char smB[3*PSTG];

    const __half* A; const __half* W; const float* bias; void* dst_; float scale;
    if (MODE == 0) {
        const int z = blockIdx.z;
        if (z == 0)      { A = A0; W = W0; bias = b0p; dst_ = d0; scale = QSCALE; }
        else if (z == 1) { A = A1; W = W1; bias = b1p; dst_ = d1; scale = 1.0f; }
        else             { A = A2; W = W2; bias = b2p; dst_ = d2; scale = 1.0f; }
    } else {
        A = A0; W = W0; bias = b0p; dst_ = d0; scale = 1.0f;
    }

    const int bm = blockIdx.y * 128;
    const int bn = blockIdx.x * 128;
    const int tid = threadIdx.x;
    const int warp = tid >> 5;
    const int lane = tid & 31;
    const int wm = warp >> 2;
    const int wn = warp & 3;
    const int g  = lane >> 2;
    const int t2 = (lane & 3) * 2;
    const int a_r  = lane & 15;
    const int a_cc = (lane >> 4) & 1;
    const int r8    = lane & 7;
    const int sel_k = (lane >> 3) & 1;
    const int sel_n = (lane >> 4) & 1;

    float acc[4][4][4] = {};

    auto stage = [&](int kt, int s) {
        const int k0 = kt * 32;
#pragma unroll
        for (int i = 0; i < 2; i++) {
            const int idx = tid + 256*i;
            const int r = idx >> 2, c = idx & 3;
            const unsigned off = swz64((unsigned)(r*64 + c*16));
            cp16(smA + s*PSTG + off, A + (size_t)(bm + r) * Ee + k0 + c*8);
            cp16(smB + s*PSTG + off, W + (size_t)(bn + r) * Ee + k0 + c*8);
        }
    };

    const int NK = Ee/32;
    stage(0, 0); cp_commit();
    stage(1, 1); cp_commit();

    for (int kt = 0; kt < NK; kt++) {
        if (kt + 1 < NK) cp_wait<1>(); else cp_wait<0>();
        __syncthreads();
        if (kt + 2 < NK) { stage(kt + 2, (kt + 2) % 3); cp_commit(); }

        const unsigned char* Ab = smA + (kt % 3) * PSTG;
        const unsigned char* Bbp = smB + (kt % 3) * PSTG;

#pragma unroll
        for (int ks = 0; ks < 2; ks++) {
            const int ck = ks * 2;
            unsigned af[4][4], bf[4][2];
#pragma unroll
            for (int mt = 0; mt < 4; mt++) {
                const int row = wm*64 + mt*16 + a_r;
                ldsm_x4(af[mt][0], af[mt][1], af[mt][2], af[mt][3],
                        (const __half*)(Ab + swz64((unsigned)(row*64 + (ck + a_cc)*16))));
            }
#pragma unroll
            for (int ntp = 0; ntp < 2; ntp++) {
                const int row = wn*32 + ntp*16 + sel_n*8 + r8;
                ldsm_x4(bf[2*ntp][0], bf[2*ntp][1], bf[2*ntp+1][0], bf[2*ntp+1][1],
                        (const __half*)(Bbp + swz64((unsigned)(row*64 + (ck + sel_k)*16))));
            }
#pragma unroll
            for (int mt = 0; mt < 4; mt++)
#pragma unroll
                for (int nt = 0; nt < 4; nt++)
                    mma16816(acc[mt][nt][0], acc[mt][nt][1], acc[mt][nt][2], acc[mt][nt][3],
                             af[mt][0], af[mt][1], af[mt][2], af[mt][3],
                             bf[nt][0], bf[nt][1]);
        }
    }

#pragma unroll
    for (int mt = 0; mt < 4; mt++) {
#pragma unroll
        for (int nt = 0; nt < 4; nt++) {
            const int row = bm + wm*64 + mt*16 + g;
            const int col = bn + wn*32 + nt*8 + t2;
#pragma unroll
            for (int hm = 0; hm < 2; hm++) {
                const int m = row + hm*8;
                const float v0 = acc[mt][nt][hm*2 + 0] + bias[col];
                const float v1 = acc[mt][nt][hm*2 + 1] + bias[col + 1];
                if (MODE == 0) {
                    __half* dst = (__half*)dst_;
                    const int b = m >> 11, s = m & 2047;
                    const int h = col >> 6, d = col & 63;
                    *(__half2*)&dst[(((size_t)(b*Hh + h))*Ss + s)*Dd + d] =
                        __floats2half2_rn(v0*scale, v1*scale);
                } else {
                    float* dst = (float*)dst_;
                    *(float2*)&dst[(size_t)m * Ee + col] = make_float2(v0, v1);
                }
            }
        }
    }
}

// ============================================================================
// Fused attention: 128 thr / 128 q-rows per CTA (warp = 32 rows), 3 CTAs/SM.
// Pass 2 restructured: per-16-key groups (QK -> exp -> store -> PV) to cut
// live registers (acc[2][2][4] instead of [2][8][4]).
// ============================================================================
#define CH 64
#define NCH (Ss/CH)
#define SLOT (64*72)
#define ATTN_SMEM (6*SLOT*2)         // 55,296 B (Q staged in slots 4-5)

__global__ __launch_bounds__(128, 3)
void attn_kernel(const __half* __restrict__ Qh, const __half* __restrict__ Kh,
                 const __half* __restrict__ Vh, float* __restrict__ attn,
                 __half* __restrict__ ctx)
{
    extern __shared__ __align__(16) __half sh[];

    const int bh = blockIdx.y;
    const int bm = blockIdx.x * 128;
    const __half* Qb = Qh + (size_t)bh * Ss * Dd;
    const __half* Kb = Kh + (size_t)bh * Ss * Dd;
    const __half* Vb = Vh + (size_t)bh * Ss * Dd;
    float* Ob = attn + (size_t)bh * Ss * Ss;

    const int tid = threadIdx.x;
    const int warp = tid >> 5;
    const int lane = tid & 31;
    const int g  = lane >> 2;
    const int t2 = (lane & 3) * 2;
    const int rw = warp * 32;            // warp covers 32 q-rows (2 m-tiles)
    const int r8    = lane & 7;
    const int sel_k = (lane >> 3) & 1;
    const int sel_n = (lane >> 4) & 1;

    auto load_k = [&](int kt, int p) {
#pragma unroll
        for (int i = 0; i < 4; i++) {
            const int idx = tid + 128*i;
            const int r = idx >> 3, c8 = (idx & 7) * 8;
            cp16(&sh[p*SLOT + r*72 + c8], Kb + (size_t)(kt*CH + r)*Dd + c8);
        }
    };
    auto load_v = [&](int kt, int p) {
#pragma unroll
        for (int i = 0; i < 4; i++) {
            const int idx = tid + 128*i;
            const int r = idx >> 3, c8 = (idx & 7) * 8;
            cp16(&sh[(3+p)*SLOT + r*72 + c8], Vb + (size_t)(kt*CH + r)*Dd + c8);
        }
    };

    // ---- stage Q (128 rows) into slots 4-5 ----
#pragma unroll
    for (int i = 0; i < 8; i++) {
        const int idx = tid + 128*i;               // 0..1023
        const int r = idx >> 3, c8 = (idx & 7) * 8;
        cp16(&sh[4*SLOT + r*72 + c8], Qb + (size_t)(bm + r)*Dd + c8);
    }
    cp_commit();
    load_k(0, 0); cp_commit();
    load_k(1, 1); cp_commit();
    load_k(2, 2); cp_commit();

    cp_wait<3>();
    __syncthreads();
    unsigned af_q[2][4][4];
    {
        const int qc = ((lane >> 4) & 1) * 8;
#pragma unroll
        for (int m = 0; m < 2; m++) {
            const int qr = rw + m*16 + (lane & 15);
#pragma unroll
            for (int kc = 0; kc < 4; kc++)
                ldsm_x4(af_q[m][kc][0], af_q[m][kc][1], af_q[m][kc][2], af_q[m][kc][3],
                        &sh[4*SLOT + qr*72 + kc*16 + qc]);
        }
    }

    float lsum[2][2] = {};

    // =================== pass 1: row sums via f16x2 ex2 ===================
    for (int kt = 0; kt < NCH; kt++) {
        if      (kt + 2 < NCH) cp_wait<2>();
        else if (kt + 1 < NCH) cp_wait<1>();
        else                   cp_wait<0>();
        __syncthreads();
        if (kt + 3 < NCH) { load_k(kt + 3, (kt + 3) & 3); cp_commit(); }

        const __half* Kt = &sh[(kt & 3)*SLOT];
#pragma unroll
        for (int kc2 = 0; kc2 < 4; kc2++) {
            float a2[2][2][4];
#pragma unroll
            for (int m = 0; m < 2; m++)
#pragma unroll
                for (int j = 0; j < 2; j++)
                    a2[m][j][0] = a2[m][j][1] = a2[m][j][2] = a2[m][j][3] = 0.f;
#pragma unroll
            for (int kc = 0; kc < 4; kc++) {
                unsigned b0, b1, b2, b3;
                ldsm_x4(b0, b1, b2, b3,
                        Kt + (kc2*16 + sel_n*8 + r8)*72 + kc*16 + sel_k*8);
#pragma unroll
                for (int m = 0; m < 2; m++) {
                    mma16816(a2[m][0][0], a2[m][0][1], a2[m][0][2], a2[m][0][3],
                             af_q[m][kc][0], af_q[m][kc][1],
                             af_q[m][kc][2], af_q[m][kc][3], b0, b1);
                    mma16816(a2[m][1][0], a2[m][1][1], a2[m][1][2], a2[m][1][3],
                             af_q[m][kc][0], af_q[m][kc][1],
                             af_q[m][kc][2], af_q[m][kc][3], b2, b3);
                }
            }
#pragma unroll
            for (int m = 0; m < 2; m++)
#pragma unroll
                for (int j = 0; j < 2; j++) {
                    unsigned e01 = h2ex2(f2h2(a2[m][j][0], a2[m][j][1]));
                    unsigned e23 = h2ex2(f2h2(a2[m][j][2], a2[m][j][3]));
                    float2 f01 = __half22float2(*(__half2*)&e01);
                    float2 f23 = __half22float2(*(__half2*)&e23);
                    lsum[m][0] += f01.x + f01.y;
                    lsum[m][1] += f23.x + f23.y;
                }
        }
    }
    float inv[2][2];
#pragma unroll
    for (int m = 0; m < 2; m++)
#pragma unroll
        for (int hrow = 0; hrow < 2; hrow++) {
            float s = lsum[m][hrow];
            s += __shfl_xor_sync(0xffffffffu, s, 1);
            s += __shfl_xor_sync(0xffffffffu, s, 2);
            inv[m][hrow] = 1.0f / s;
        }

    __syncthreads();

    // =================== pass 2: per-16-key groups, low live regs ===========
    float cacc[2][8][4];
#pragma unroll
    for (int m = 0; m < 2; m++)
#pragma unroll
        for (int dt = 0; dt < 8; dt++)
            cacc[m][dt][0] = cacc[m][dt][1] = cacc[m][dt][2] = cacc[m][dt][3] = 0.f;

    load_k(0, 0); load_v(0, 0); cp_commit();
    load_k(1, 1); load_v(1, 1); cp_commit();

    for (int kt = 0; kt < NCH; kt++) {
        if (kt + 1 < NCH) cp_wait<1>(); else cp_wait<0>();
        __syncthreads();
        if (kt + 2 < NCH) {
            load_k(kt + 2, (kt + 2) % 3);
            load_v(kt + 2, (kt + 2) % 3);
            cp_commit();
        }

        const __half* Kt = &sh[(kt % 3)*SLOT];
        const __half* Vt = &sh[(3 + kt % 3)*SLOT];

#pragma unroll
        for (int kc2 = 0; kc2 < 4; kc2++) {
            // --- QK for this 16-key group ---
            float a2[2][2][4];
#pragma unroll
            for (int m = 0; m < 2; m++)
#pragma unroll
                for (int j = 0; j < 2; j++)
                    a2[m][j][0] = a2[m][j][1] = a2[m][j][2] = a2[m][j][3] = 0.f;
#pragma unroll
            for (int kc = 0; kc < 4; kc++) {
                unsigned b0, b1, b2, b3;
                ldsm_x4(b0, b1, b2, b3,
                        Kt + (kc2*16 + sel_n*8 + r8)*72 + kc*16 + sel_k*8);
#pragma unroll
                for (int m = 0; m < 2; m++) {
                    mma16816(a2[m][0][0], a2[m][0][1], a2[m][0][2], a2[m][0][3],
                             af_q[m][kc][0], af_q[m][kc][1],
                             af_q[m][kc][2], af_q[m][kc][3], b0, b1);
                    mma16816(a2[m][1][0], a2[m][1][1], a2[m][1][2], a2[m][1][3],
                             af_q[m][kc][0], af_q[m][kc][1],
                             af_q[m][kc][2], af_q[m][kc][3], b2, b3);
                }
            }

            // --- exp, normalize, store attn ---
            unsigned pa[2][4];
#pragma unroll
            for (int m = 0; m < 2; m++) {
                const int row0 = bm + rw + m*16 + g;
#pragma unroll
                for (int j = 0; j < 2; j++) {
                    const float p0 = ex2f(a2[m][j][0]) * inv[m][0];
                    const float p1 = ex2f(a2[m][j][1]) * inv[m][0];
                    const float p2 = ex2f(a2[m][j][2]) * inv[m][1];
                    const float p3 = ex2f(a2[m][j][3]) * inv[m][1];
                    const int col = kt*CH + kc2*16 + j*8 + t2;
                    stg_cs_v2(Ob + (size_t)row0 * Ss + col, p0, p1);
                    stg_cs_v2(Ob + (size_t)(row0 + 8) * Ss + col, p2, p3);
                    a2[m][j][0] = p0; a2[m][j][1] = p1;
                    a2[m][j][2] = p2; a2[m][j][3] = p3;
                }
                pa[m][0] = f2h2(a2[m][0][0], a2[m][0][1]);
                pa[m][1] = f2h2(a2[m][0][2], a2[m][0][3]);
                pa[m][2] = f2h2(a2[m][1][0], a2[m][1][1]);
                pa[m][3] = f2h2(a2[m][1][2], a2[m][1][3]);
            }

            // --- P·V for this 16-key group ---
#pragma unroll
            for (int dtp = 0; dtp < 4; dtp++) {
                unsigned b0, b1, b2, b3;
                ldsm_x4t(b0, b1, b2, b3,
                         Vt + (kc2*16 + sel_k*8 + r8)*72 + (dtp*2 + sel_n)*8);
#pragma unroll
                for (int m = 0; m < 2; m++) {
                    mma16816(cacc[m][2*dtp][0], cacc[m][2*dtp][1],
                             cacc[m][2*dtp][2], cacc[m][2*dtp][3],
                             pa[m][0], pa[m][1], pa[m][2], pa[m][3], b0, b1);
                    mma16816(cacc[m][2*dtp+1][0], cacc[m][2*dtp+1][1],
                             cacc[m][2*dtp+1][2], cacc[m][2*dtp+1][3],
                             pa[m][0], pa[m][1], pa[m][2], pa[m][3], b2, b3);
                }
            }
        }
    }

    // ---- epilogue: ctx (fp16) ----
    const int b = bh >> 4;
    const int h = bh & 15;
#pragma unroll
    for (int m = 0; m < 2; m++) {
        const int s0 = bm + rw + m*16 + g;
#pragma unroll
        for (int dt = 0; dt < 8; dt++) {
            const int d = dt*8 + t2;
            *(__half2*)(ctx + ((size_t)b * Ss + s0    ) * Ee + h*Dd + d) =
                __floats2half2_rn(cacc[m][dt][0], cacc[m][dt][1]);
            *(__half2*)(ctx + ((size_t)b * Ss + s0 + 8) * Ee + h*Dd + d) =
                __floats2half2_rn(cacc[m][dt][2], cacc[m][dt][3]);
        }
    }
}

// ============================================================================
extern "C" void kernel_launch(void* const* d_in, const int* in_sizes, int n_in,
                              void* d_out, int out_size)
{
    const float* query  = (const float*)d_in[0];
    const float* key_in = (const float*)d_in[1];
    const float* value  = (const float*)d_in[2];
    const float* Wq = (const float*)d_in[3];
    const float* bq = (const float*)d_in[4];
    const float* Wk = (const float*)d_in[5];
    const float* bk = (const float*)d_in[6];
    const float* Wv = (const float*)d_in[7];
    const float* bv = (const float*)d_in[8];
    const float* Wo = (const float*)d_in[9];
    const float* bo = (const float*)d_in[10];

    float* out = (float*)d_out;

    __half *xq, *xk, *xv, *wq, *wk, *wv, *wo, *Qh, *Kh, *Vh, *ctxh;
    float *attn;
    cudaGetSymbolAddress((void**)&xq, g_xq);
    cudaGetSymbolAddress((void**)&xk, g_xk);
    cudaGetSymbolAddress((void**)&xv, g_xv);
    cudaGetSymbolAddress((void**)&wq, g_wq);
    cudaGetSymbolAddress((void**)&wk, g_wk);
    cudaGetSymbolAddress((void**)&wv, g_wv);
    cudaGetSymbolAddress((void**)&wo, g_wo);
    cudaGetSymbolAddress((void**)&Qh, g_Qh);
    cudaGetSymbolAddress((void**)&Kh, g_Kh);
    cudaGetSymbolAddress((void**)&Vh, g_Vh);
    cudaGetSymbolAddress((void**)&ctxh, g_ctxh);

    const size_t BSE = (size_t)Bb * Ss * Ee;
    if ((size_t)out_size > BSE) {
        attn = out + BSE;
    } else {
        cudaGetSymbolAddress((void**)&attn, g_attn_fb);
    }

    cudaFuncSetAttribute(attn_kernel,
                         cudaFuncAttributeMaxDynamicSharedMemorySize, ATTN_SMEM);

    f2h_all_kernel<<<3*IN_BLK + 4*W_BLK, 256>>>(query, key_in, value, Wq, Wk, Wv, Wo,
                                                xq, xk, xv, wq, wk, wv, wo);

    proj16_kernel<0><<<dim3(Ee/128, MTOK/128, 3), 256>>>(
        xq, xk, xv, wq, wk, wv, bq, bk, bv, Qh, Kh, Vh);

    attn_kernel<<<dim3(Ss/128, BH), 128, ATTN_SMEM>>>(Qh, Kh, Vh, attn, ctxh);

    proj16_kernel<1><<<dim3(Ee/128, MTOK/128, 1), 256>>>(
        ctxh, nullptr, nullptr, wo, nullptr, nullptr,
        bo, nullptr, nullptr, out, nullptr, nullptr);
}